// round 12
// baseline (speedup 1.0000x reference)
#include <cuda_runtime.h>
#include <math.h>
#include <stdint.h>
#include <mma.h>

using namespace nvcuda;

#define NN   100000
#define EE   800000
#define NLB  200000

// ---------------------------------------------------------------------------
// Scratch (static device globals — allocation-free, graph-capture safe)
// ---------------------------------------------------------------------------
__device__ float    g_h0  [(size_t)NN * 256];
__device__ float    g_out0[(size_t)NN * 64];
__device__ float    g_h1  [(size_t)NN * 128];
__device__ float    g_out1[(size_t)NN * 32];
__device__ float    g_z   [(size_t)NN * 32];
__device__ float    g_asrc[(size_t)NN * 4];
__device__ float    g_adst[(size_t)NN * 4];
__device__ float    g_den [(size_t)NN * 4];
__device__ float    g_acsr[(size_t)EE * 4];   // exp(e) in CSR order
__device__ float    g_e1  [(size_t)NN * 32];
__device__ float    g_e2  [(size_t)NN * 64];
__device__ float    g_e3  [(size_t)NN * 96];
// CSR by destination (built once per call, shared by both GAT layers)
__device__ int      g_deg   [NN];
__device__ int      g_rowptr[NN + 1];
__device__ int      g_cursor[NN];
__device__ int      g_csrsrc[EE];
__device__ int      g_csrpos[EE];

static inline int cdiv(long long a, long long b) { return (int)((a + b - 1) / b); }

// ---------------------------------------------------------------------------
// CSR construction
// ---------------------------------------------------------------------------
__global__ void deg_reset(int* deg, int n) {
    int i = blockIdx.x * blockDim.x + threadIdx.x;
    if (i < n) deg[i] = 0;
}
__global__ void deg_count(const int* __restrict__ ei, int* __restrict__ deg, int E) {
    int e = blockIdx.x * blockDim.x + threadIdx.x;
    if (e < E) atomicAdd(deg + ei[E + e], 1);
}
__global__ __launch_bounds__(1024)
void scan_kernel(const int* __restrict__ deg, int* __restrict__ rowptr,
                 int* __restrict__ cursor, int n)
{
    __shared__ int part[1024];
    int tid = threadIdx.x;
    int chunk = (n + 1023) / 1024;
    int base = tid * chunk;
    int s = 0;
    for (int i = 0; i < chunk; i++) {
        int idx = base + i;
        if (idx < n) s += deg[idx];
    }
    part[tid] = s;
    __syncthreads();
    for (int off = 1; off < 1024; off <<= 1) {
        int v = (tid >= off) ? part[tid - off] : 0;
        __syncthreads();
        part[tid] += v;
        __syncthreads();
    }
    int run = (tid == 0) ? 0 : part[tid - 1];
    for (int i = 0; i < chunk; i++) {
        int idx = base + i;
        if (idx < n) {
            rowptr[idx] = run;
            cursor[idx] = run;
            run += deg[idx];
        }
    }
    if (tid == 0) rowptr[n] = part[1023];
}
__global__ void csr_scatter(const int* __restrict__ ei, int* __restrict__ cursor,
                            int* __restrict__ csrsrc, int* __restrict__ csrpos, int E)
{
    int e = blockIdx.x * blockDim.x + threadIdx.x;
    if (e >= E) return;
    int d = ei[E + e];
    int pos = atomicAdd(cursor + d, 1);
    csrsrc[pos] = ei[e];
    csrpos[e]   = pos;
}

// ---------------------------------------------------------------------------
// Resets / small transforms
// ---------------------------------------------------------------------------
__global__ void reset_den(float* den, int n) {
    int i = blockIdx.x * blockDim.x + threadIdx.x;
    if (i < n) den[i] = 0.f;
}
// den -> 0.25/(den+eps): folds softmax normalization AND the head-mean 0.25.
__global__ void invden_kernel(float* den, int n) {
    int i = blockIdx.x * blockDim.x + threadIdx.x;
    if (i < n) den[i] = 0.25f / (den[i] + 1e-16f);
}

// ---------------------------------------------------------------------------
// sgemm64: BM=BN=64, BK=16, 256 threads, 4x4 micro-tile (small-N layers).
// ---------------------------------------------------------------------------
__global__ __launch_bounds__(256)
void sgemm64(const float* __restrict__ A, const float* __restrict__ B,
             const float* __restrict__ bias, float* __restrict__ C,
             int M, int N, int K, int relu)
{
    const int BM = 64, BN = 64, BK = 16;
    __shared__ __align__(16) float As[BK][BM + 4];
    __shared__ __align__(16) float Bs[BK][BN];

    int tid = threadIdx.x;
    int tx  = tid & 15;
    int ty  = tid >> 4;
    int rowBase = blockIdx.y * BM;
    int colBase = blockIdx.x * BN;
    int ar = tid >> 2;
    int ac = (tid & 3) * 4;

    float acc[4][4] = {};

    for (int k0 = 0; k0 < K; k0 += BK) {
        float4 av = make_float4(0.f, 0.f, 0.f, 0.f);
        int gr = rowBase + ar;
        if (gr < M) av = *(const float4*)(A + (size_t)gr * K + k0 + ac);
        As[ac + 0][ar] = av.x; As[ac + 1][ar] = av.y;
        As[ac + 2][ar] = av.z; As[ac + 3][ar] = av.w;

        #pragma unroll
        for (int i = 0; i < 4; i++) {
            int idx = tid + i * 256;
            int r = idx >> 6, c = idx & 63;
            int gc = colBase + c;
            Bs[r][c] = (gc < N) ? B[(size_t)(k0 + r) * N + gc] : 0.f;
        }
        __syncthreads();

        #pragma unroll
        for (int k = 0; k < BK; k++) {
            float4 a4 = *(const float4*)&As[k][ty * 4];
            float4 b4 = *(const float4*)&Bs[k][tx * 4];
            float am[4] = {a4.x, a4.y, a4.z, a4.w};
            float bm[4] = {b4.x, b4.y, b4.z, b4.w};
            #pragma unroll
            for (int m = 0; m < 4; m++)
                #pragma unroll
                for (int n = 0; n < 4; n++)
                    acc[m][n] += am[m] * bm[n];
        }
        __syncthreads();
    }

    #pragma unroll
    for (int m = 0; m < 4; m++) {
        int gr = rowBase + ty * 4 + m;
        if (gr >= M) continue;
        #pragma unroll
        for (int n = 0; n < 4; n++) {
            int gc = colBase + tx * 4 + n;
            if (gc >= N) continue;
            float v = acc[m][n];
            if (bias) v += bias[gc];
            if (relu) v = fmaxf(v, 0.f);
            C[(size_t)gr * N + gc] = v;
        }
    }
}

// ---------------------------------------------------------------------------
// sgemm128: BM=BN=128, BK=8, warp-tiled 8x8 micro-tile, conflict-free LDS.
// (R9 winner — kept for h0/h1.)
// ---------------------------------------------------------------------------
__global__ __launch_bounds__(256, 2)
void sgemm128(const float* __restrict__ A, const float* __restrict__ B,
              const float* __restrict__ bias, float* __restrict__ C,
              int M, int N, int K, int relu)
{
    const int BM = 128, BN = 128, BK = 8;
    __shared__ __align__(16) float As[BK][BM + 4];
    __shared__ __align__(16) float Bs[BK][BN];

    int tid  = threadIdx.x;
    int wid  = tid >> 5, lane = tid & 31;
    int wm   = wid & 3;
    int wn   = wid >> 2;
    int r    = lane >> 3;
    int c    = lane & 7;
    int rowBase = blockIdx.y * BM;
    int colBase = blockIdx.x * BN;

    int trow  = wm * 32 + r * 8;
    int tcol0 = wn * 64 + c * 4;
    int tcol1 = wn * 64 + 32 + c * 4;

    int ar = tid >> 1;
    int ac = (tid & 1) * 4;
    int br = tid >> 5;
    int bc = (tid & 31) * 4;

    float acc[8][8] = {};

    for (int k0 = 0; k0 < K; k0 += BK) {
        float4 av = make_float4(0.f, 0.f, 0.f, 0.f);
        int gr = rowBase + ar;
        if (gr < M) av = *(const float4*)(A + (size_t)gr * K + k0 + ac);
        As[ac + 0][ar] = av.x; As[ac + 1][ar] = av.y;
        As[ac + 2][ar] = av.z; As[ac + 3][ar] = av.w;

        int gc = colBase + bc;
        float4 bv;
        if (gc + 3 < N) {
            bv = *(const float4*)(B + (size_t)(k0 + br) * N + gc);
        } else {
            bv.x = (gc + 0 < N) ? B[(size_t)(k0 + br) * N + gc + 0] : 0.f;
            bv.y = (gc + 1 < N) ? B[(size_t)(k0 + br) * N + gc + 1] : 0.f;
            bv.z = (gc + 2 < N) ? B[(size_t)(k0 + br) * N + gc + 2] : 0.f;
            bv.w = (gc + 3 < N) ? B[(size_t)(k0 + br) * N + gc + 3] : 0.f;
        }
        *(float4*)&Bs[br][bc] = bv;
        __syncthreads();

        #pragma unroll
        for (int k = 0; k < BK; k++) {
            float a[8], b[8];
            *(float4*)&a[0] = *(const float4*)&As[k][trow];
            *(float4*)&a[4] = *(const float4*)&As[k][trow + 4];
            *(float4*)&b[0] = *(const float4*)&Bs[k][tcol0];
            *(float4*)&b[4] = *(const float4*)&Bs[k][tcol1];
            #pragma unroll
            for (int m = 0; m < 8; m++)
                #pragma unroll
                for (int n = 0; n < 8; n++)
                    acc[m][n] += a[m] * b[n];
        }
        __syncthreads();
    }

    #pragma unroll
    for (int m = 0; m < 8; m++) {
        int gr = rowBase + trow + m;
        if (gr >= M) continue;
        #pragma unroll
        for (int half = 0; half < 2; half++) {
            int cb = (half == 0) ? tcol0 : tcol1;
            #pragma unroll
            for (int n = 0; n < 4; n++) {
                int gc = colBase + cb + n;
                if (gc >= N) continue;
                float v = acc[m][half * 4 + n];
                if (bias) v += bias[gc];
                if (relu) v = fmaxf(v, 0.f);
                C[(size_t)gr * N + gc] = v;
            }
        }
    }
}

// ---------------------------------------------------------------------------
// wgemm_tf32: 128x128 block, TF32 wmma (m16n16k8), BK=32.
// 8 warps = 4(M) x 2(N); warp tile 32x64 = 2x4 fragments.
// Used ONLY for d4 (leaf GEMM: TF32 error does not propagate).
// Epilogue stages each 16x16 tile through smem for bias + boundary guards.
// ---------------------------------------------------------------------------
__global__ __launch_bounds__(256, 2)
void wgemm_tf32(const float* __restrict__ A, const float* __restrict__ B,
                const float* __restrict__ bias, float* __restrict__ C,
                int M, int N, int K)
{
    const int BM = 128, BN = 128, BK = 32;
    __shared__ __align__(16) float As[BM][BK + 4];      // ldm 36 (144B, 16B-mult)
    __shared__ __align__(16) float Bs[BK][BN + 4];      // ldm 132 (528B, 16B-mult)
    __shared__ __align__(16) float stage[8][16][20];    // per-warp epilogue tile

    int tid = threadIdx.x;
    int wid = tid >> 5, lane = tid & 31;
    int wm = wid & 3;            // 0..3 -> 32-row group
    int wn = wid >> 2;           // 0..1 -> 64-col group
    int rowBase = blockIdx.y * BM;
    int colBase = blockIdx.x * BN;

    wmma::fragment<wmma::accumulator, 16, 16, 8, float> acc[2][4];
    #pragma unroll
    for (int m = 0; m < 2; m++)
        #pragma unroll
        for (int n = 0; n < 4; n++)
            wmma::fill_fragment(acc[m][n], 0.f);

    for (int k0 = 0; k0 < K; k0 += BK) {
        // A: 128x32 tile = 1024 float4, 4 per thread
        #pragma unroll
        for (int i = 0; i < 4; i++) {
            int idx = tid + i * 256;
            int r = idx >> 3, c4 = (idx & 7) * 4;
            int gr = rowBase + r;
            float4 v = make_float4(0.f, 0.f, 0.f, 0.f);
            if (gr < M && k0 + c4 < K)
                v = *(const float4*)(A + (size_t)gr * K + k0 + c4);
            *(float4*)&As[r][c4] = v;
        }
        // B: 32x128 tile = 1024 float4, 4 per thread
        #pragma unroll
        for (int i = 0; i < 4; i++) {
            int idx = tid + i * 256;
            int r = idx >> 5, c4 = (idx & 31) * 4;
            int gc = colBase + c4;
            int gk = k0 + r;
            float4 v = make_float4(0.f, 0.f, 0.f, 0.f);
            if (gk < K) {
                if (gc + 3 < N) {
                    v = *(const float4*)(B + (size_t)gk * N + gc);
                } else {
                    if (gc + 0 < N) v.x = B[(size_t)gk * N + gc + 0];
                    if (gc + 1 < N) v.y = B[(size_t)gk * N + gc + 1];
                    if (gc + 2 < N) v.z = B[(size_t)gk * N + gc + 2];
                    if (gc + 3 < N) v.w = B[(size_t)gk * N + gc + 3];
                }
            }
            *(float4*)&Bs[r][c4] = v;
        }
        __syncthreads();

        #pragma unroll
        for (int kk = 0; kk < BK; kk += 8) {
            wmma::fragment<wmma::matrix_a, 16, 16, 8, wmma::precision::tf32, wmma::row_major> af[2];
            wmma::fragment<wmma::matrix_b, 16, 16, 8, wmma::precision::tf32, wmma::row_major> bf[4];
            #pragma unroll
            for (int m = 0; m < 2; m++) {
                wmma::load_matrix_sync(af[m], &As[wm * 32 + m * 16][kk], BK + 4);
                #pragma unroll
                for (int t = 0; t < af[m].num_elements; t++)
                    af[m].x[t] = wmma::__float_to_tf32(af[m].x[t]);
            }
            #pragma unroll
            for (int n = 0; n < 4; n++) {
                wmma::load_matrix_sync(bf[n], &Bs[kk][wn * 64 + n * 16], BN + 4);
                #pragma unroll
                for (int t = 0; t < bf[n].num_elements; t++)
                    bf[n].x[t] = wmma::__float_to_tf32(bf[n].x[t]);
            }
            #pragma unroll
            for (int m = 0; m < 2; m++)
                #pragma unroll
                for (int n = 0; n < 4; n++)
                    wmma::mma_sync(acc[m][n], af[m], bf[n], acc[m][n]);
        }
        __syncthreads();
    }

    // Epilogue: stage each 16x16 tile in smem, add bias, guarded store.
    int er = lane >> 1;              // 0..15
    int ec = (lane & 1) * 8;         // 0 or 8
    #pragma unroll
    for (int m = 0; m < 2; m++) {
        #pragma unroll
        for (int n = 0; n < 4; n++) {
            wmma::store_matrix_sync(&stage[wid][0][0], acc[m][n], 20, wmma::mem_row_major);
            __syncwarp();
            int gr  = rowBase + wm * 32 + m * 16 + er;
            int gcb = colBase + wn * 64 + n * 16 + ec;
            if (gr < M) {
                #pragma unroll
                for (int j = 0; j < 8; j++) {
                    int gc = gcb + j;
                    if (gc < N)
                        C[(size_t)gr * N + gc] = stage[wid][er][ec + j] + bias[gc];
                }
            }
            __syncwarp();
        }
    }
}

// ---------------------------------------------------------------------------
// Per-node attention logits (warp per node)
// ---------------------------------------------------------------------------
template <int C>
__global__ void alpha_kernel(const float* __restrict__ h,
                             const float* __restrict__ a_s,
                             const float* __restrict__ a_d,
                             float* __restrict__ asrc, float* __restrict__ adst, int N)
{
    int gw   = (int)((blockIdx.x * (long long)blockDim.x + threadIdx.x) >> 5);
    int lane = threadIdx.x & 31;
    if (gw >= N) return;
    const float* hr = h + (size_t)gw * 4 * C;
    #pragma unroll
    for (int hh = 0; hh < 4; hh++) {
        float s1 = 0.f, s2 = 0.f;
        #pragma unroll
        for (int c = lane; c < C; c += 32) {
            float hv = hr[hh * C + c];
            s1 += hv * a_s[hh * C + c];
            s2 += hv * a_d[hh * C + c];
        }
        #pragma unroll
        for (int o = 16; o; o >>= 1) {
            s1 += __shfl_down_sync(0xffffffffu, s1, o);
            s2 += __shfl_down_sync(0xffffffffu, s2, o);
        }
        if (lane == 0) {
            asrc[(size_t)gw * 4 + hh] = s1;
            adst[(size_t)gw * 4 + hh] = s2;
        }
    }
}

// ---------------------------------------------------------------------------
// Single edge pass: exp(leaky_relu(asrc[s]+adst[d])) straight into CSR order;
// denominator accumulated with one v4 RED.
// ---------------------------------------------------------------------------
__device__ __forceinline__ float leaky02(float v) { return v > 0.f ? v : 0.2f * v; }

__global__ void edge_exp_kernel(const int* __restrict__ ei,
                                const float* __restrict__ asrc,
                                const float* __restrict__ adst,
                                const int* __restrict__ csrpos,
                                float* __restrict__ acsr,
                                float* __restrict__ den, int E)
{
    int e = blockIdx.x * blockDim.x + threadIdx.x;
    if (e >= E) return;
    int s = ei[e], d = ei[E + e];
    float4 a = *(const float4*)(asrc + (size_t)s * 4);
    float4 b = *(const float4*)(adst + (size_t)d * 4);
    float ex0 = __expf(leaky02(a.x + b.x));
    float ex1 = __expf(leaky02(a.y + b.y));
    float ex2 = __expf(leaky02(a.z + b.z));
    float ex3 = __expf(leaky02(a.w + b.w));
    int pos = csrpos[e];
    *(float4*)(acsr + (size_t)pos * 4) = make_float4(ex0, ex1, ex2, ex3);
    float* dp = den + (size_t)d * 4;
    asm volatile("red.global.add.v4.f32 [%0], {%1,%2,%3,%4};"
                 :: "l"(dp), "f"(ex0), "f"(ex1), "f"(ex2), "f"(ex3)
                 : "memory");
}

// ---------------------------------------------------------------------------
// CSR gather aggregation + softmax normalization + head-mean + bias + relu.
// ---------------------------------------------------------------------------
template <int C>
__global__ void gather_kernel(const int* __restrict__ rowptr,
                              const int* __restrict__ csrsrc,
                              const float* __restrict__ acsr,
                              const float* __restrict__ dinv,
                              const float* __restrict__ h,
                              const float* __restrict__ bias,
                              float* __restrict__ out, int N)
{
    constexpr int P = (4 * C) / 32;
    int gw   = (int)((blockIdx.x * (long long)blockDim.x + threadIdx.x) >> 5);
    int lane = threadIdx.x & 31;
    if (gw >= N) return;

    int beg = rowptr[gw], end = rowptr[gw + 1];
    int hh = lane >> 3;

    float acc[P];
    #pragma unroll
    for (int i = 0; i < P; i++) acc[i] = 0.f;

    for (int j = beg; j < end; j++) {
        int s = csrsrc[j];
        float al = acsr[(size_t)j * 4 + hh];
        const float4* hp = (const float4*)(h + (size_t)s * 4 * C + lane * P);
        #pragma unroll
        for (int q = 0; q < P / 4; q++) {
            float4 hv = hp[q];
            acc[q * 4 + 0] += hv.x * al;
            acc[q * 4 + 1] += hv.y * al;
            acc[q * 4 + 2] += hv.z * al;
            acc[q * 4 + 3] += hv.w * al;
        }
    }

    float di = dinv[(size_t)gw * 4 + hh];
    #pragma unroll
    for (int i = 0; i < P; i++) acc[i] *= di;

    #pragma unroll
    for (int o = 8; o < 32; o <<= 1)
        #pragma unroll
        for (int i = 0; i < P; i++)
            acc[i] += __shfl_xor_sync(0xffffffffu, acc[i], o);

    if (lane < 8) {
        int cb = lane * P;
        #pragma unroll
        for (int q = 0; q < P / 4; q++) {
            float4 v;
            v.x = fmaxf(acc[q * 4 + 0] + bias[cb + q * 4 + 0], 0.f);
            v.y = fmaxf(acc[q * 4 + 1] + bias[cb + q * 4 + 1], 0.f);
            v.z = fmaxf(acc[q * 4 + 2] + bias[cb + q * 4 + 2], 0.f);
            v.w = fmaxf(acc[q * 4 + 3] + bias[cb + q * 4 + 3], 0.f);
            *(float4*)(out + (size_t)gw * C + cb + q * 4) = v;
        }
    }
}

__global__ void link_kernel(const int* __restrict__ eli, const float* __restrict__ z,
                            float* __restrict__ out, int NL)
{
    int i = blockIdx.x * blockDim.x + threadIdx.x;
    if (i >= NL) return;
    int a = eli[i], b = eli[NL + i];
    const float4* za = (const float4*)(z + (size_t)a * 32);
    const float4* zb = (const float4*)(z + (size_t)b * 32);
    float s = 0.f;
    #pragma unroll
    for (int j = 0; j < 8; j++) {
        float4 u = za[j], v = zb[j];
        s += u.x * v.x + u.y * v.y + u.z * v.z + u.w * v.w;
    }
    out[i] = s;
}

// ---------------------------------------------------------------------------
// Launch
// ---------------------------------------------------------------------------
extern "C" void kernel_launch(void* const* d_in, const int* in_sizes, int n_in,
                              void* d_out, int out_size)
{
    const float* x   = (const float*)d_in[0];
    const int*   ei  = (const int*)  d_in[1];
    const int*   eli = (const int*)  d_in[2];
    const float* W0  = (const float*)d_in[3];
    const float* as0 = (const float*)d_in[4];
    const float* ad0 = (const float*)d_in[5];
    const float* b0  = (const float*)d_in[6];
    const float* W1  = (const float*)d_in[7];
    const float* as1 = (const float*)d_in[8];
    const float* ad1 = (const float*)d_in[9];
    const float* b1  = (const float*)d_in[10];
    const float* lw  = (const float*)d_in[11];
    const float* lb  = (const float*)d_in[12];
    const float* d1w = (const float*)d_in[13];
    const float* d1b = (const float*)d_in[14];
    const float* d2w = (const float*)d_in[15];
    const float* d2b = (const float*)d_in[16];
    const float* d3w = (const float*)d_in[17];
    const float* d3b = (const float*)d_in[18];
    const float* d4w = (const float*)d_in[19];
    const float* d4b = (const float*)d_in[20];

    int N  = in_sizes[0] / 64;
    int E  = in_sizes[1] / 2;
    int NL = in_sizes[2] / 2;
    float* out = (float*)d_out;

    float *h0, *out0, *h1, *out1, *z, *asrc, *adst, *den, *acsr, *e1, *e2, *e3;
    int *deg, *rowptr, *cursor, *csrsrc, *csrpos;
    cudaGetSymbolAddress((void**)&h0,   g_h0);
    cudaGetSymbolAddress((void**)&out0, g_out0);
    cudaGetSymbolAddress((void**)&h1,   g_h1);
    cudaGetSymbolAddress((void**)&out1, g_out1);
    cudaGetSymbolAddress((void**)&z,    g_z);
    cudaGetSymbolAddress((void**)&asrc, g_asrc);
    cudaGetSymbolAddress((void**)&adst, g_adst);
    cudaGetSymbolAddress((void**)&den,  g_den);
    cudaGetSymbolAddress((void**)&acsr, g_acsr);
    cudaGetSymbolAddress((void**)&e1,   g_e1);
    cudaGetSymbolAddress((void**)&e2,   g_e2);
    cudaGetSymbolAddress((void**)&e3,   g_e3);
    cudaGetSymbolAddress((void**)&deg,    g_deg);
    cudaGetSymbolAddress((void**)&rowptr, g_rowptr);
    cudaGetSymbolAddress((void**)&cursor, g_cursor);
    cudaGetSymbolAddress((void**)&csrsrc, g_csrsrc);
    cudaGetSymbolAddress((void**)&csrpos, g_csrpos);

    dim3 blk(256);
    int gNH   = cdiv((long long)N * 4, 256);
    int gE    = cdiv(E, 256);
    int gN    = cdiv(N, 256);
    int gR64  = cdiv(N, 64);
    int gR128 = cdiv(N, 128);
    int gWarp = cdiv((long long)N * 32, 256);

    // ------------------ CSR build (shared by both layers) ------------------
    deg_reset  <<<gN, blk>>>(deg, N);
    deg_count  <<<gE, blk>>>(ei, deg, E);
    scan_kernel<<<1, 1024>>>(deg, rowptr, cursor, N);
    csr_scatter<<<gE, blk>>>(ei, cursor, csrsrc, csrpos, E);

    // ------------------ GAT layer 0 (64 -> 4 x 64) ------------------
    sgemm128<<<dim3(2, gR128), blk>>>(x, W0, nullptr, h0, N, 256, 64, 0);
    alpha_kernel<64><<<cdiv(N, 8), blk>>>(h0, as0, ad0, asrc, adst, N);
    reset_den<<<gNH, blk>>>(den, N * 4);
    edge_exp_kernel<<<gE, blk>>>(ei, asrc, adst, csrpos, acsr, den, E);
    invden_kernel<<<gNH, blk>>>(den, N * 4);
    gather_kernel<64><<<gWarp, blk>>>(rowptr, csrsrc, acsr, den, h0, b0, out0, N);

    // ------------------ GAT layer 1 (64 -> 4 x 32) ------------------
    sgemm128<<<dim3(1, gR128), blk>>>(out0, W1, nullptr, h1, N, 128, 64, 0);
    alpha_kernel<32><<<cdiv(N, 8), blk>>>(h1, as1, ad1, asrc, adst, N);
    reset_den<<<gNH, blk>>>(den, N * 4);
    edge_exp_kernel<<<gE, blk>>>(ei, asrc, adst, csrpos, acsr, den, E);
    invden_kernel<<<gNH, blk>>>(den, N * 4);
    gather_kernel<32><<<gWarp, blk>>>(rowptr, csrsrc, acsr, den, h1, b1, out1, N);

    // ------------------ z = out1 @ lin_w + lin_b ------------------
    sgemm64<<<dim3(1, gR64), blk>>>(out1, lw, lb, z, N, 32, 32, 0);

    // ------------------ link decode -> d_out[0 : NL] ------------------
    link_kernel<<<cdiv(NL, 256), blk>>>(eli, z, out, NL);

    // ------------------ expression MLP -> d_out[NL : ] ------------------
    sgemm64<<<dim3(1, gR64), blk>>>(z,  d1w, d1b, e1, N, 32,  32, 1);
    sgemm64<<<dim3(1, gR64), blk>>>(e1, d2w, d2b, e2, N, 64,  32, 1);
    sgemm64<<<dim3(2, gR64), blk>>>(e2, d3w, d3b, e3, N, 96,  64, 1);
    wgemm_tf32<<<dim3(4, gR128), blk>>>(e3, d4w, d4b, out + NL, N, 500, 96);
}

// round 13
// speedup vs baseline: 1.0626x; 1.0626x over previous
#include <cuda_runtime.h>
#include <math.h>
#include <stdint.h>

#define NN   100000
#define EE   800000
#define NLB  200000

// ---------------------------------------------------------------------------
// Scratch (static device globals — allocation-free, graph-capture safe)
// ---------------------------------------------------------------------------
__device__ float    g_h0  [(size_t)NN * 256];
__device__ float    g_out0[(size_t)NN * 64];
__device__ float    g_h1  [(size_t)NN * 128];
__device__ float    g_out1[(size_t)NN * 32];
__device__ float    g_z   [(size_t)NN * 32];
__device__ float    g_asrc[(size_t)NN * 4];
__device__ float    g_adst[(size_t)NN * 4];
__device__ float    g_e1  [(size_t)NN * 32];
__device__ float    g_e2  [(size_t)NN * 64];
__device__ float    g_e3  [(size_t)NN * 96];
// CSR by destination (built once per call, shared by both GAT layers)
__device__ int      g_deg   [NN];
__device__ int      g_rowptr[NN + 1];
__device__ int      g_cursor[NN];
__device__ int      g_csrsrc[EE];

static inline int cdiv(long long a, long long b) { return (int)((a + b - 1) / b); }

// ---------------------------------------------------------------------------
// CSR construction
// ---------------------------------------------------------------------------
__global__ void deg_reset(int* deg, int n) {
    int i = blockIdx.x * blockDim.x + threadIdx.x;
    if (i < n) deg[i] = 0;
}
__global__ void deg_count(const int* __restrict__ ei, int* __restrict__ deg, int E) {
    int e = blockIdx.x * blockDim.x + threadIdx.x;
    if (e < E) atomicAdd(deg + ei[E + e], 1);
}
__global__ __launch_bounds__(1024)
void scan_kernel(const int* __restrict__ deg, int* __restrict__ rowptr,
                 int* __restrict__ cursor, int n)
{
    __shared__ int part[1024];
    int tid = threadIdx.x;
    int chunk = (n + 1023) / 1024;
    int base = tid * chunk;
    int s = 0;
    for (int i = 0; i < chunk; i++) {
        int idx = base + i;
        if (idx < n) s += deg[idx];
    }
    part[tid] = s;
    __syncthreads();
    for (int off = 1; off < 1024; off <<= 1) {
        int v = (tid >= off) ? part[tid - off] : 0;
        __syncthreads();
        part[tid] += v;
        __syncthreads();
    }
    int run = (tid == 0) ? 0 : part[tid - 1];
    for (int i = 0; i < chunk; i++) {
        int idx = base + i;
        if (idx < n) {
            rowptr[idx] = run;
            cursor[idx] = run;
            run += deg[idx];
        }
    }
    if (tid == 0) rowptr[n] = part[1023];
}
__global__ void csr_scatter(const int* __restrict__ ei, int* __restrict__ cursor,
                            int* __restrict__ csrsrc, int E)
{
    int e = blockIdx.x * blockDim.x + threadIdx.x;
    if (e >= E) return;
    int d = ei[E + e];
    int pos = atomicAdd(cursor + d, 1);
    csrsrc[pos] = ei[e];
}

// ---------------------------------------------------------------------------
// sgemm64: BM=BN=64, BK=16, 256 threads, 4x4 micro-tile (small-N layers).
// ---------------------------------------------------------------------------
__global__ __launch_bounds__(256)
void sgemm64(const float* __restrict__ A, const float* __restrict__ B,
             const float* __restrict__ bias, float* __restrict__ C,
             int M, int N, int K, int relu)
{
    const int BM = 64, BN = 64, BK = 16;
    __shared__ __align__(16) float As[BK][BM + 4];
    __shared__ __align__(16) float Bs[BK][BN];

    int tid = threadIdx.x;
    int tx  = tid & 15;
    int ty  = tid >> 4;
    int rowBase = blockIdx.y * BM;
    int colBase = blockIdx.x * BN;
    int ar = tid >> 2;
    int ac = (tid & 3) * 4;

    float acc[4][4] = {};

    for (int k0 = 0; k0 < K; k0 += BK) {
        float4 av = make_float4(0.f, 0.f, 0.f, 0.f);
        int gr = rowBase + ar;
        if (gr < M) av = *(const float4*)(A + (size_t)gr * K + k0 + ac);
        As[ac + 0][ar] = av.x; As[ac + 1][ar] = av.y;
        As[ac + 2][ar] = av.z; As[ac + 3][ar] = av.w;

        #pragma unroll
        for (int i = 0; i < 4; i++) {
            int idx = tid + i * 256;
            int r = idx >> 6, c = idx & 63;
            int gc = colBase + c;
            Bs[r][c] = (gc < N) ? B[(size_t)(k0 + r) * N + gc] : 0.f;
        }
        __syncthreads();

        #pragma unroll
        for (int k = 0; k < BK; k++) {
            float4 a4 = *(const float4*)&As[k][ty * 4];
            float4 b4 = *(const float4*)&Bs[k][tx * 4];
            float am[4] = {a4.x, a4.y, a4.z, a4.w};
            float bm[4] = {b4.x, b4.y, b4.z, b4.w};
            #pragma unroll
            for (int m = 0; m < 4; m++)
                #pragma unroll
                for (int n = 0; n < 4; n++)
                    acc[m][n] += am[m] * bm[n];
        }
        __syncthreads();
    }

    #pragma unroll
    for (int m = 0; m < 4; m++) {
        int gr = rowBase + ty * 4 + m;
        if (gr >= M) continue;
        #pragma unroll
        for (int n = 0; n < 4; n++) {
            int gc = colBase + tx * 4 + n;
            if (gc >= N) continue;
            float v = acc[m][n];
            if (bias) v += bias[gc];
            if (relu) v = fmaxf(v, 0.f);
            C[(size_t)gr * N + gc] = v;
        }
    }
}

// ---------------------------------------------------------------------------
// sgemm128: BM=BN=128, BK=8, warp-tiled 8x8 micro-tile, conflict-free LDS.
// (R9 winner — h0/h1/d4.)
// ---------------------------------------------------------------------------
__global__ __launch_bounds__(256, 2)
void sgemm128(const float* __restrict__ A, const float* __restrict__ B,
              const float* __restrict__ bias, float* __restrict__ C,
              int M, int N, int K, int relu)
{
    const int BM = 128, BN = 128, BK = 8;
    __shared__ __align__(16) float As[BK][BM + 4];
    __shared__ __align__(16) float Bs[BK][BN];

    int tid  = threadIdx.x;
    int wid  = tid >> 5, lane = tid & 31;
    int wm   = wid & 3;
    int wn   = wid >> 2;
    int r    = lane >> 3;
    int c    = lane & 7;
    int rowBase = blockIdx.y * BM;
    int colBase = blockIdx.x * BN;

    int trow  = wm * 32 + r * 8;
    int tcol0 = wn * 64 + c * 4;
    int tcol1 = wn * 64 + 32 + c * 4;

    int ar = tid >> 1;
    int ac = (tid & 1) * 4;
    int br = tid >> 5;
    int bc = (tid & 31) * 4;

    float acc[8][8] = {};

    for (int k0 = 0; k0 < K; k0 += BK) {
        float4 av = make_float4(0.f, 0.f, 0.f, 0.f);
        int gr = rowBase + ar;
        if (gr < M) av = *(const float4*)(A + (size_t)gr * K + k0 + ac);
        As[ac + 0][ar] = av.x; As[ac + 1][ar] = av.y;
        As[ac + 2][ar] = av.z; As[ac + 3][ar] = av.w;

        int gc = colBase + bc;
        float4 bv;
        if (gc + 3 < N) {
            bv = *(const float4*)(B + (size_t)(k0 + br) * N + gc);
        } else {
            bv.x = (gc + 0 < N) ? B[(size_t)(k0 + br) * N + gc + 0] : 0.f;
            bv.y = (gc + 1 < N) ? B[(size_t)(k0 + br) * N + gc + 1] : 0.f;
            bv.z = (gc + 2 < N) ? B[(size_t)(k0 + br) * N + gc + 2] : 0.f;
            bv.w = (gc + 3 < N) ? B[(size_t)(k0 + br) * N + gc + 3] : 0.f;
        }
        *(float4*)&Bs[br][bc] = bv;
        __syncthreads();

        #pragma unroll
        for (int k = 0; k < BK; k++) {
            float a[8], b[8];
            *(float4*)&a[0] = *(const float4*)&As[k][trow];
            *(float4*)&a[4] = *(const float4*)&As[k][trow + 4];
            *(float4*)&b[0] = *(const float4*)&Bs[k][tcol0];
            *(float4*)&b[4] = *(const float4*)&Bs[k][tcol1];
            #pragma unroll
            for (int m = 0; m < 8; m++)
                #pragma unroll
                for (int n = 0; n < 8; n++)
                    acc[m][n] += a[m] * b[n];
        }
        __syncthreads();
    }

    #pragma unroll
    for (int m = 0; m < 8; m++) {
        int gr = rowBase + trow + m;
        if (gr >= M) continue;
        #pragma unroll
        for (int half = 0; half < 2; half++) {
            int cb = (half == 0) ? tcol0 : tcol1;
            #pragma unroll
            for (int n = 0; n < 4; n++) {
                int gc = colBase + cb + n;
                if (gc >= N) continue;
                float v = acc[m][half * 4 + n];
                if (bias) v += bias[gc];
                if (relu) v = fmaxf(v, 0.f);
                C[(size_t)gr * N + gc] = v;
            }
        }
    }
}

// ---------------------------------------------------------------------------
// Per-node attention logits (warp per node)
// ---------------------------------------------------------------------------
template <int C>
__global__ void alpha_kernel(const float* __restrict__ h,
                             const float* __restrict__ a_s,
                             const float* __restrict__ a_d,
                             float* __restrict__ asrc, float* __restrict__ adst, int N)
{
    int gw   = (int)((blockIdx.x * (long long)blockDim.x + threadIdx.x) >> 5);
    int lane = threadIdx.x & 31;
    if (gw >= N) return;
    const float* hr = h + (size_t)gw * 4 * C;
    #pragma unroll
    for (int hh = 0; hh < 4; hh++) {
        float s1 = 0.f, s2 = 0.f;
        #pragma unroll
        for (int c = lane; c < C; c += 32) {
            float hv = hr[hh * C + c];
            s1 += hv * a_s[hh * C + c];
            s2 += hv * a_d[hh * C + c];
        }
        #pragma unroll
        for (int o = 16; o; o >>= 1) {
            s1 += __shfl_down_sync(0xffffffffu, s1, o);
            s2 += __shfl_down_sync(0xffffffffu, s2, o);
        }
        if (lane == 0) {
            asrc[(size_t)gw * 4 + hh] = s1;
            adst[(size_t)gw * 4 + hh] = s2;
        }
    }
}

// ---------------------------------------------------------------------------
// Fully-fused GAT aggregation: per-node softmax (denominator from own CSR
// row — no atomics, no E-sized intermediates) + weighted gather + head-mean
// + bias + relu. One warp per node.
//   Pass 1: lanes stride the row; each computes exp(leaky(asrc[s]+adst[gw]))
//           for all 4 heads and accumulates den[4]; warp-reduce.
//   Pass 2: all lanes walk the row together; lane recomputes its head's
//           alpha inline (1 MUFU warp-instr/edge) and accumulates h[src].
// ---------------------------------------------------------------------------
__device__ __forceinline__ float leaky02(float v) { return v > 0.f ? v : 0.2f * v; }

template <int C>
__global__ void gather_kernel(const int* __restrict__ rowptr,
                              const int* __restrict__ csrsrc,
                              const float* __restrict__ asrc,
                              const float* __restrict__ adst,
                              const float* __restrict__ h,
                              const float* __restrict__ bias,
                              float* __restrict__ out, int N)
{
    constexpr int P = (4 * C) / 32;          // floats per lane (8 for C=64, 4 for C=32)
    int gw   = (int)((blockIdx.x * (long long)blockDim.x + threadIdx.x) >> 5);
    int lane = threadIdx.x & 31;
    if (gw >= N) return;

    int beg = rowptr[gw], end = rowptr[gw + 1];
    float4 ad = *(const float4*)(adst + (size_t)gw * 4);

    // ---- Pass 1: softmax denominator for this node (register-only) ----
    float d0 = 0.f, d1 = 0.f, d2 = 0.f, d3 = 0.f;
    for (int j = beg + lane; j < end; j += 32) {
        int s = csrsrc[j];
        float4 a = *(const float4*)(asrc + (size_t)s * 4);
        d0 += __expf(leaky02(a.x + ad.x));
        d1 += __expf(leaky02(a.y + ad.y));
        d2 += __expf(leaky02(a.z + ad.z));
        d3 += __expf(leaky02(a.w + ad.w));
    }
    #pragma unroll
    for (int o = 16; o; o >>= 1) {
        d0 += __shfl_xor_sync(0xffffffffu, d0, o);
        d1 += __shfl_xor_sync(0xffffffffu, d1, o);
        d2 += __shfl_xor_sync(0xffffffffu, d2, o);
        d3 += __shfl_xor_sync(0xffffffffu, d3, o);
    }

    int hh = lane >> 3;                      // this lane's head
    float adh  = (hh == 0) ? ad.x : (hh == 1) ? ad.y : (hh == 2) ? ad.z : ad.w;
    float denh = (hh == 0) ? d0   : (hh == 1) ? d1   : (hh == 2) ? d2   : d3;
    float dinv = 0.25f / (denh + 1e-16f);    // folds head-mean 0.25

    // ---- Pass 2: weighted aggregation ----
    float acc[P];
    #pragma unroll
    for (int i = 0; i < P; i++) acc[i] = 0.f;

    for (int j = beg; j < end; j++) {
        int s = csrsrc[j];
        float al = __expf(leaky02(asrc[(size_t)s * 4 + hh] + adh));
        const float4* hp = (const float4*)(h + (size_t)s * 4 * C + lane * P);
        #pragma unroll
        for (int q = 0; q < P / 4; q++) {
            float4 hv = hp[q];
            acc[q * 4 + 0] += hv.x * al;
            acc[q * 4 + 1] += hv.y * al;
            acc[q * 4 + 2] += hv.z * al;
            acc[q * 4 + 3] += hv.w * al;
        }
    }

    #pragma unroll
    for (int i = 0; i < P; i++) acc[i] *= dinv;

    // sum across 4 heads: lanes {l, l+8, l+16, l+24} hold the same channels
    #pragma unroll
    for (int o = 8; o < 32; o <<= 1)
        #pragma unroll
        for (int i = 0; i < P; i++)
            acc[i] += __shfl_xor_sync(0xffffffffu, acc[i], o);

    if (lane < 8) {
        int cb = lane * P;
        #pragma unroll
        for (int q = 0; q < P / 4; q++) {
            float4 v;
            v.x = fmaxf(acc[q * 4 + 0] + bias[cb + q * 4 + 0], 0.f);
            v.y = fmaxf(acc[q * 4 + 1] + bias[cb + q * 4 + 1], 0.f);
            v.z = fmaxf(acc[q * 4 + 2] + bias[cb + q * 4 + 2], 0.f);
            v.w = fmaxf(acc[q * 4 + 3] + bias[cb + q * 4 + 3], 0.f);
            *(float4*)(out + (size_t)gw * C + cb + q * 4) = v;
        }
    }
}

__global__ void link_kernel(const int* __restrict__ eli, const float* __restrict__ z,
                            float* __restrict__ out, int NL)
{
    int i = blockIdx.x * blockDim.x + threadIdx.x;
    if (i >= NL) return;
    int a = eli[i], b = eli[NL + i];
    const float4* za = (const float4*)(z + (size_t)a * 32);
    const float4* zb = (const float4*)(z + (size_t)b * 32);
    float s = 0.f;
    #pragma unroll
    for (int j = 0; j < 8; j++) {
        float4 u = za[j], v = zb[j];
        s += u.x * v.x + u.y * v.y + u.z * v.z + u.w * v.w;
    }
    out[i] = s;
}

// ---------------------------------------------------------------------------
// Launch
// ---------------------------------------------------------------------------
extern "C" void kernel_launch(void* const* d_in, const int* in_sizes, int n_in,
                              void* d_out, int out_size)
{
    const float* x   = (const float*)d_in[0];
    const int*   ei  = (const int*)  d_in[1];
    const int*   eli = (const int*)  d_in[2];
    const float* W0  = (const float*)d_in[3];
    const float* as0 = (const float*)d_in[4];
    const float* ad0 = (const float*)d_in[5];
    const float* b0  = (const float*)d_in[6];
    const float* W1  = (const float*)d_in[7];
    const float* as1 = (const float*)d_in[8];
    const float* ad1 = (const float*)d_in[9];
    const float* b1  = (const float*)d_in[10];
    const float* lw  = (const float*)d_in[11];
    const float* lb  = (const float*)d_in[12];
    const float* d1w = (const float*)d_in[13];
    const float* d1b = (const float*)d_in[14];
    const float* d2w = (const float*)d_in[15];
    const float* d2b = (const float*)d_in[16];
    const float* d3w = (const float*)d_in[17];
    const float* d3b = (const float*)d_in[18];
    const float* d4w = (const float*)d_in[19];
    const float* d4b = (const float*)d_in[20];

    int N  = in_sizes[0] / 64;
    int E  = in_sizes[1] / 2;
    int NL = in_sizes[2] / 2;
    float* out = (float*)d_out;

    float *h0, *out0, *h1, *out1, *z, *asrc, *adst, *e1, *e2, *e3;
    int *deg, *rowptr, *cursor, *csrsrc;
    cudaGetSymbolAddress((void**)&h0,   g_h0);
    cudaGetSymbolAddress((void**)&out0, g_out0);
    cudaGetSymbolAddress((void**)&h1,   g_h1);
    cudaGetSymbolAddress((void**)&out1, g_out1);
    cudaGetSymbolAddress((void**)&z,    g_z);
    cudaGetSymbolAddress((void**)&asrc, g_asrc);
    cudaGetSymbolAddress((void**)&adst, g_adst);
    cudaGetSymbolAddress((void**)&e1,   g_e1);
    cudaGetSymbolAddress((void**)&e2,   g_e2);
    cudaGetSymbolAddress((void**)&e3,   g_e3);
    cudaGetSymbolAddress((void**)&deg,    g_deg);
    cudaGetSymbolAddress((void**)&rowptr, g_rowptr);
    cudaGetSymbolAddress((void**)&cursor, g_cursor);
    cudaGetSymbolAddress((void**)&csrsrc, g_csrsrc);

    dim3 blk(256);
    int gE    = cdiv(E, 256);
    int gN    = cdiv(N, 256);
    int gR64  = cdiv(N, 64);
    int gR128 = cdiv(N, 128);
    int gWarp = cdiv((long long)N * 32, 256);

    // ------------------ CSR build (shared by both layers) ------------------
    deg_reset  <<<gN, blk>>>(deg, N);
    deg_count  <<<gE, blk>>>(ei, deg, E);
    scan_kernel<<<1, 1024>>>(deg, rowptr, cursor, N);
    csr_scatter<<<gE, blk>>>(ei, cursor, csrsrc, E);

    // ------------------ GAT layer 0 (64 -> 4 x 64) ------------------
    sgemm128<<<dim3(2, gR128), blk>>>(x, W0, nullptr, h0, N, 256, 64, 0);
    alpha_kernel<64><<<cdiv(N, 8), blk>>>(h0, as0, ad0, asrc, adst, N);
    gather_kernel<64><<<gWarp, blk>>>(rowptr, csrsrc, asrc, adst, h0, b0, out0, N);

    // ------------------ GAT layer 1 (64 -> 4 x 32) ------------------
    sgemm128<<<dim3(1, gR128), blk>>>(out0, W1, nullptr, h1, N, 128, 64, 0);
    alpha_kernel<32><<<cdiv(N, 8), blk>>>(h1, as1, ad1, asrc, adst, N);
    gather_kernel<32><<<gWarp, blk>>>(rowptr, csrsrc, asrc, adst, h1, b1, out1, N);

    // ------------------ z = out1 @ lin_w + lin_b ------------------
    sgemm64<<<dim3(1, gR64), blk>>>(out1, lw, lb, z, N, 32, 32, 0);

    // ------------------ link decode -> d_out[0 : NL] ------------------
    link_kernel<<<cdiv(NL, 256), blk>>>(eli, z, out, NL);

    // ------------------ expression MLP -> d_out[NL : ] ------------------
    sgemm64 <<<dim3(1, gR64),  blk>>>(z,  d1w, d1b, e1, N, 32,  32, 1);
    sgemm64 <<<dim3(1, gR64),  blk>>>(e1, d2w, d2b, e2, N, 64,  32, 1);
    sgemm64 <<<dim3(2, gR64),  blk>>>(e2, d3w, d3b, e3, N, 96,  64, 1);
    sgemm128<<<dim3(4, gR128), blk>>>(e3, d4w, d4b, out + NL, N, 500, 96, 0);
}

// round 14
// speedup vs baseline: 1.0969x; 1.0323x over previous
#include <cuda_runtime.h>
#include <math.h>
#include <stdint.h>

#define NN   100000
#define EE   800000
#define NLB  200000

// ---------------------------------------------------------------------------
// Scratch (static device globals — allocation-free, graph-capture safe)
// ---------------------------------------------------------------------------
__device__ float    g_h0  [(size_t)NN * 256];
__device__ float    g_out0[(size_t)NN * 64];
__device__ float    g_h1  [(size_t)NN * 128];
__device__ float    g_out1[(size_t)NN * 32];
__device__ float    g_z   [(size_t)NN * 32];
__device__ float    g_asrc[(size_t)NN * 4];
__device__ float    g_adst[(size_t)NN * 4];
__device__ float    g_e1  [(size_t)NN * 32];
__device__ float    g_e2  [(size_t)NN * 64];
__device__ float    g_e3  [(size_t)NN * 96];
// CSR by destination (built once per call, shared by both GAT layers)
__device__ int      g_deg   [NN];
__device__ int      g_rowptr[NN + 1];
__device__ int      g_cursor[NN];
__device__ int      g_csrsrc[EE];

static inline int cdiv(long long a, long long b) { return (int)((a + b - 1) / b); }

// ---------------------------------------------------------------------------
// CSR construction
// ---------------------------------------------------------------------------
__global__ void deg_reset(int* deg, int n) {
    int i = blockIdx.x * blockDim.x + threadIdx.x;
    if (i < n) deg[i] = 0;
}
__global__ void deg_count(const int* __restrict__ ei, int* __restrict__ deg, int E) {
    int e = blockIdx.x * blockDim.x + threadIdx.x;
    if (e < E) atomicAdd(deg + ei[E + e], 1);
}
__global__ __launch_bounds__(1024)
void scan_kernel(const int* __restrict__ deg, int* __restrict__ rowptr,
                 int* __restrict__ cursor, int n)
{
    __shared__ int part[1024];
    int tid = threadIdx.x;
    int chunk = (n + 1023) / 1024;
    int base = tid * chunk;
    int s = 0;
    for (int i = 0; i < chunk; i++) {
        int idx = base + i;
        if (idx < n) s += deg[idx];
    }
    part[tid] = s;
    __syncthreads();
    for (int off = 1; off < 1024; off <<= 1) {
        int v = (tid >= off) ? part[tid - off] : 0;
        __syncthreads();
        part[tid] += v;
        __syncthreads();
    }
    int run = (tid == 0) ? 0 : part[tid - 1];
    for (int i = 0; i < chunk; i++) {
        int idx = base + i;
        if (idx < n) {
            rowptr[idx] = run;
            cursor[idx] = run;
            run += deg[idx];
        }
    }
    if (tid == 0) rowptr[n] = part[1023];
}
__global__ void csr_scatter(const int* __restrict__ ei, int* __restrict__ cursor,
                            int* __restrict__ csrsrc, int E)
{
    int e = blockIdx.x * blockDim.x + threadIdx.x;
    if (e >= E) return;
    int d = ei[E + e];
    int pos = atomicAdd(cursor + d, 1);
    csrsrc[pos] = ei[e];
}

// ---------------------------------------------------------------------------
// sgemm64: BM=BN=64, BK=16, 256 threads, 4x4 micro-tile (small-N layers).
// ---------------------------------------------------------------------------
__global__ __launch_bounds__(256)
void sgemm64(const float* __restrict__ A, const float* __restrict__ B,
             const float* __restrict__ bias, float* __restrict__ C,
             int M, int N, int K, int relu)
{
    const int BM = 64, BN = 64, BK = 16;
    __shared__ __align__(16) float As[BK][BM + 4];
    __shared__ __align__(16) float Bs[BK][BN];

    int tid = threadIdx.x;
    int tx  = tid & 15;
    int ty  = tid >> 4;
    int rowBase = blockIdx.y * BM;
    int colBase = blockIdx.x * BN;
    int ar = tid >> 2;
    int ac = (tid & 3) * 4;

    float acc[4][4] = {};

    for (int k0 = 0; k0 < K; k0 += BK) {
        float4 av = make_float4(0.f, 0.f, 0.f, 0.f);
        int gr = rowBase + ar;
        if (gr < M) av = *(const float4*)(A + (size_t)gr * K + k0 + ac);
        As[ac + 0][ar] = av.x; As[ac + 1][ar] = av.y;
        As[ac + 2][ar] = av.z; As[ac + 3][ar] = av.w;

        #pragma unroll
        for (int i = 0; i < 4; i++) {
            int idx = tid + i * 256;
            int r = idx >> 6, c = idx & 63;
            int gc = colBase + c;
            Bs[r][c] = (gc < N) ? B[(size_t)(k0 + r) * N + gc] : 0.f;
        }
        __syncthreads();

        #pragma unroll
        for (int k = 0; k < BK; k++) {
            float4 a4 = *(const float4*)&As[k][ty * 4];
            float4 b4 = *(const float4*)&Bs[k][tx * 4];
            float am[4] = {a4.x, a4.y, a4.z, a4.w};
            float bm[4] = {b4.x, b4.y, b4.z, b4.w};
            #pragma unroll
            for (int m = 0; m < 4; m++)
                #pragma unroll
                for (int n = 0; n < 4; n++)
                    acc[m][n] += am[m] * bm[n];
        }
        __syncthreads();
    }

    #pragma unroll
    for (int m = 0; m < 4; m++) {
        int gr = rowBase + ty * 4 + m;
        if (gr >= M) continue;
        #pragma unroll
        for (int n = 0; n < 4; n++) {
            int gc = colBase + tx * 4 + n;
            if (gc >= N) continue;
            float v = acc[m][n];
            if (bias) v += bias[gc];
            if (relu) v = fmaxf(v, 0.f);
            C[(size_t)gr * N + gc] = v;
        }
    }
}

// ---------------------------------------------------------------------------
// sgemm128: BM=BN=128, BK=8, warp-tiled 8x8 micro-tile, conflict-free LDS.
// (R9 winner — h0/h1/d4.)
// ---------------------------------------------------------------------------
__global__ __launch_bounds__(256, 2)
void sgemm128(const float* __restrict__ A, const float* __restrict__ B,
              const float* __restrict__ bias, float* __restrict__ C,
              int M, int N, int K, int relu)
{
    const int BM = 128, BN = 128, BK = 8;
    __shared__ __align__(16) float As[BK][BM + 4];
    __shared__ __align__(16) float Bs[BK][BN];

    int tid  = threadIdx.x;
    int wid  = tid >> 5, lane = tid & 31;
    int wm   = wid & 3;
    int wn   = wid >> 2;
    int r    = lane >> 3;
    int c    = lane & 7;
    int rowBase = blockIdx.y * BM;
    int colBase = blockIdx.x * BN;

    int trow  = wm * 32 + r * 8;
    int tcol0 = wn * 64 + c * 4;
    int tcol1 = wn * 64 + 32 + c * 4;

    int ar = tid >> 1;
    int ac = (tid & 1) * 4;
    int br = tid >> 5;
    int bc = (tid & 31) * 4;

    float acc[8][8] = {};

    for (int k0 = 0; k0 < K; k0 += BK) {
        float4 av = make_float4(0.f, 0.f, 0.f, 0.f);
        int gr = rowBase + ar;
        if (gr < M) av = *(const float4*)(A + (size_t)gr * K + k0 + ac);
        As[ac + 0][ar] = av.x; As[ac + 1][ar] = av.y;
        As[ac + 2][ar] = av.z; As[ac + 3][ar] = av.w;

        int gc = colBase + bc;
        float4 bv;
        if (gc + 3 < N) {
            bv = *(const float4*)(B + (size_t)(k0 + br) * N + gc);
        } else {
            bv.x = (gc + 0 < N) ? B[(size_t)(k0 + br) * N + gc + 0] : 0.f;
            bv.y = (gc + 1 < N) ? B[(size_t)(k0 + br) * N + gc + 1] : 0.f;
            bv.z = (gc + 2 < N) ? B[(size_t)(k0 + br) * N + gc + 2] : 0.f;
            bv.w = (gc + 3 < N) ? B[(size_t)(k0 + br) * N + gc + 3] : 0.f;
        }
        *(float4*)&Bs[br][bc] = bv;
        __syncthreads();

        #pragma unroll
        for (int k = 0; k < BK; k++) {
            float a[8], b[8];
            *(float4*)&a[0] = *(const float4*)&As[k][trow];
            *(float4*)&a[4] = *(const float4*)&As[k][trow + 4];
            *(float4*)&b[0] = *(const float4*)&Bs[k][tcol0];
            *(float4*)&b[4] = *(const float4*)&Bs[k][tcol1];
            #pragma unroll
            for (int m = 0; m < 8; m++)
                #pragma unroll
                for (int n = 0; n < 8; n++)
                    acc[m][n] += a[m] * b[n];
        }
        __syncthreads();
    }

    #pragma unroll
    for (int m = 0; m < 8; m++) {
        int gr = rowBase + trow + m;
        if (gr >= M) continue;
        #pragma unroll
        for (int half = 0; half < 2; half++) {
            int cb = (half == 0) ? tcol0 : tcol1;
            #pragma unroll
            for (int n = 0; n < 4; n++) {
                int gc = colBase + cb + n;
                if (gc >= N) continue;
                float v = acc[m][half * 4 + n];
                if (bias) v += bias[gc];
                if (relu) v = fmaxf(v, 0.f);
                C[(size_t)gr * N + gc] = v;
            }
        }
    }
}

// ---------------------------------------------------------------------------
// Per-node attention logits (warp per node)
// ---------------------------------------------------------------------------
template <int C>
__global__ void alpha_kernel(const float* __restrict__ h,
                             const float* __restrict__ a_s,
                             const float* __restrict__ a_d,
                             float* __restrict__ asrc, float* __restrict__ adst, int N)
{
    int gw   = (int)((blockIdx.x * (long long)blockDim.x + threadIdx.x) >> 5);
    int lane = threadIdx.x & 31;
    if (gw >= N) return;
    const float* hr = h + (size_t)gw * 4 * C;
    #pragma unroll
    for (int hh = 0; hh < 4; hh++) {
        float s1 = 0.f, s2 = 0.f;
        #pragma unroll
        for (int c = lane; c < C; c += 32) {
            float hv = hr[hh * C + c];
            s1 += hv * a_s[hh * C + c];
            s2 += hv * a_d[hh * C + c];
        }
        #pragma unroll
        for (int o = 16; o; o >>= 1) {
            s1 += __shfl_down_sync(0xffffffffu, s1, o);
            s2 += __shfl_down_sync(0xffffffffu, s2, o);
        }
        if (lane == 0) {
            asrc[(size_t)gw * 4 + hh] = s1;
            adst[(size_t)gw * 4 + hh] = s2;
        }
    }
}

// ---------------------------------------------------------------------------
// Single-pass fused GAT aggregation. One warp per node.
// Key invariant: all 8 lanes of head hh compute the IDENTICAL alpha for each
// edge, so each lane accumulates the softmax denominator (den += al) as a
// private scalar during the aggregation walk — no separate denominator pass,
// no warp reduction for den. Normalize once after the loop, then reduce
// across heads and store (bias + relu fused).
// ---------------------------------------------------------------------------
__device__ __forceinline__ float leaky02(float v) { return v > 0.f ? v : 0.2f * v; }

template <int C>
__global__ void gather_kernel(const int* __restrict__ rowptr,
                              const int* __restrict__ csrsrc,
                              const float* __restrict__ asrc,
                              const float* __restrict__ adst,
                              const float* __restrict__ h,
                              const float* __restrict__ bias,
                              float* __restrict__ out, int N)
{
    constexpr int P = (4 * C) / 32;          // floats per lane (8 for C=64, 4 for C=32)
    int gw   = (int)((blockIdx.x * (long long)blockDim.x + threadIdx.x) >> 5);
    int lane = threadIdx.x & 31;
    if (gw >= N) return;

    int beg = rowptr[gw], end = rowptr[gw + 1];
    int hh = lane >> 3;                      // this lane's head
    float adh = adst[(size_t)gw * 4 + hh];

    float acc[P];
    #pragma unroll
    for (int i = 0; i < P; i++) acc[i] = 0.f;
    float den = 0.f;

    for (int j = beg; j < end; j++) {
        int s = csrsrc[j];
        float al = __expf(leaky02(asrc[(size_t)s * 4 + hh] + adh));
        den += al;
        const float4* hp = (const float4*)(h + (size_t)s * 4 * C + lane * P);
        #pragma unroll
        for (int q = 0; q < P / 4; q++) {
            float4 hv = hp[q];
            acc[q * 4 + 0] += hv.x * al;
            acc[q * 4 + 1] += hv.y * al;
            acc[q * 4 + 2] += hv.z * al;
            acc[q * 4 + 3] += hv.w * al;
        }
    }

    float dinv = 0.25f / (den + 1e-16f);     // folds head-mean 0.25
    #pragma unroll
    for (int i = 0; i < P; i++) acc[i] *= dinv;

    // sum across 4 heads: lanes {l, l+8, l+16, l+24} hold the same channels
    #pragma unroll
    for (int o = 8; o < 32; o <<= 1)
        #pragma unroll
        for (int i = 0; i < P; i++)
            acc[i] += __shfl_xor_sync(0xffffffffu, acc[i], o);

    if (lane < 8) {
        int cb = lane * P;
        #pragma unroll
        for (int q = 0; q < P / 4; q++) {
            float4 v;
            v.x = fmaxf(acc[q * 4 + 0] + bias[cb + q * 4 + 0], 0.f);
            v.y = fmaxf(acc[q * 4 + 1] + bias[cb + q * 4 + 1], 0.f);
            v.z = fmaxf(acc[q * 4 + 2] + bias[cb + q * 4 + 2], 0.f);
            v.w = fmaxf(acc[q * 4 + 3] + bias[cb + q * 4 + 3], 0.f);
            *(float4*)(out + (size_t)gw * C + cb + q * 4) = v;
        }
    }
}

__global__ void link_kernel(const int* __restrict__ eli, const float* __restrict__ z,
                            float* __restrict__ out, int NL)
{
    int i = blockIdx.x * blockDim.x + threadIdx.x;
    if (i >= NL) return;
    int a = eli[i], b = eli[NL + i];
    const float4* za = (const float4*)(z + (size_t)a * 32);
    const float4* zb = (const float4*)(z + (size_t)b * 32);
    float s = 0.f;
    #pragma unroll
    for (int j = 0; j < 8; j++) {
        float4 u = za[j], v = zb[j];
        s += u.x * v.x + u.y * v.y + u.z * v.z + u.w * v.w;
    }
    out[i] = s;
}

// ---------------------------------------------------------------------------
// Launch
// ---------------------------------------------------------------------------
extern "C" void kernel_launch(void* const* d_in, const int* in_sizes, int n_in,
                              void* d_out, int out_size)
{
    const float* x   = (const float*)d_in[0];
    const int*   ei  = (const int*)  d_in[1];
    const int*   eli = (const int*)  d_in[2];
    const float* W0  = (const float*)d_in[3];
    const float* as0 = (const float*)d_in[4];
    const float* ad0 = (const float*)d_in[5];
    const float* b0  = (const float*)d_in[6];
    const float* W1  = (const float*)d_in[7];
    const float* as1 = (const float*)d_in[8];
    const float* ad1 = (const float*)d_in[9];
    const float* b1  = (const float*)d_in[10];
    const float* lw  = (const float*)d_in[11];
    const float* lb  = (const float*)d_in[12];
    const float* d1w = (const float*)d_in[13];
    const float* d1b = (const float*)d_in[14];
    const float* d2w = (const float*)d_in[15];
    const float* d2b = (const float*)d_in[16];
    const float* d3w = (const float*)d_in[17];
    const float* d3b = (const float*)d_in[18];
    const float* d4w = (const float*)d_in[19];
    const float* d4b = (const float*)d_in[20];

    int N  = in_sizes[0] / 64;
    int E  = in_sizes[1] / 2;
    int NL = in_sizes[2] / 2;
    float* out = (float*)d_out;

    float *h0, *out0, *h1, *out1, *z, *asrc, *adst, *e1, *e2, *e3;
    int *deg, *rowptr, *cursor, *csrsrc;
    cudaGetSymbolAddress((void**)&h0,   g_h0);
    cudaGetSymbolAddress((void**)&out0, g_out0);
    cudaGetSymbolAddress((void**)&h1,   g_h1);
    cudaGetSymbolAddress((void**)&out1, g_out1);
    cudaGetSymbolAddress((void**)&z,    g_z);
    cudaGetSymbolAddress((void**)&asrc, g_asrc);
    cudaGetSymbolAddress((void**)&adst, g_adst);
    cudaGetSymbolAddress((void**)&e1,   g_e1);
    cudaGetSymbolAddress((void**)&e2,   g_e2);
    cudaGetSymbolAddress((void**)&e3,   g_e3);
    cudaGetSymbolAddress((void**)&deg,    g_deg);
    cudaGetSymbolAddress((void**)&rowptr, g_rowptr);
    cudaGetSymbolAddress((void**)&cursor, g_cursor);
    cudaGetSymbolAddress((void**)&csrsrc, g_csrsrc);

    dim3 blk(256);
    int gE    = cdiv(E, 256);
    int gN    = cdiv(N, 256);
    int gR64  = cdiv(N, 64);
    int gR128 = cdiv(N, 128);
    int gWarp = cdiv((long long)N * 32, 256);

    // ------------------ CSR build (shared by both layers) ------------------
    deg_reset  <<<gN, blk>>>(deg, N);
    deg_count  <<<gE, blk>>>(ei, deg, E);
    scan_kernel<<<1, 1024>>>(deg, rowptr, cursor, N);
    csr_scatter<<<gE, blk>>>(ei, cursor, csrsrc, E);

    // ------------------ GAT layer 0 (64 -> 4 x 64) ------------------
    sgemm128<<<dim3(2, gR128), blk>>>(x, W0, nullptr, h0, N, 256, 64, 0);
    alpha_kernel<64><<<cdiv(N, 8), blk>>>(h0, as0, ad0, asrc, adst, N);
    gather_kernel<64><<<gWarp, blk>>>(rowptr, csrsrc, asrc, adst, h0, b0, out0, N);

    // ------------------ GAT layer 1 (64 -> 4 x 32) ------------------
    sgemm128<<<dim3(1, gR128), blk>>>(out0, W1, nullptr, h1, N, 128, 64, 0);
    alpha_kernel<32><<<cdiv(N, 8), blk>>>(h1, as1, ad1, asrc, adst, N);
    gather_kernel<32><<<gWarp, blk>>>(rowptr, csrsrc, asrc, adst, h1, b1, out1, N);

    // ------------------ z = out1 @ lin_w + lin_b ------------------
    sgemm64<<<dim3(1, gR64), blk>>>(out1, lw, lb, z, N, 32, 32, 0);

    // ------------------ link decode -> d_out[0 : NL] ------------------
    link_kernel<<<cdiv(NL, 256), blk>>>(eli, z, out, NL);

    // ------------------ expression MLP -> d_out[NL : ] ------------------
    sgemm64 <<<dim3(1, gR64),  blk>>>(z,  d1w, d1b, e1, N, 32,  32, 1);
    sgemm64 <<<dim3(1, gR64),  blk>>>(e1, d2w, d2b, e2, N, 64,  32, 1);
    sgemm64 <<<dim3(2, gR64),  blk>>>(e2, d3w, d3b, e3, N, 96,  64, 1);
    sgemm128<<<dim3(4, gR128), blk>>>(e3, d4w, d4b, out + NL, N, 500, 96, 0);
}

// round 15
// speedup vs baseline: 1.1236x; 1.0243x over previous
#include <cuda_runtime.h>
#include <math.h>
#include <stdint.h>

#define NN   100000
#define EE   800000
#define NLB  200000

// ---------------------------------------------------------------------------
// Scratch (static device globals — allocation-free, graph-capture safe)
// ---------------------------------------------------------------------------
__device__ float    g_X4  [(size_t)NN * 256];  // per-head aggregated x (layer 0)
__device__ float    g_out0[(size_t)NN * 64];
__device__ float    g_h1  [(size_t)NN * 128];
__device__ float    g_out1[(size_t)NN * 32];
__device__ float    g_z   [(size_t)NN * 32];
__device__ float    g_asrc[(size_t)NN * 4];
__device__ float    g_adst[(size_t)NN * 4];
__device__ float    g_wt  [512];               // w~s[4][64] then w~d[4][64]
__device__ float    g_e1  [(size_t)NN * 32];
__device__ float    g_e2  [(size_t)NN * 64];
__device__ float    g_e3  [(size_t)NN * 96];
// CSR by destination (built once per call, shared by both GAT layers)
__device__ int      g_deg   [NN];
__device__ int      g_rowptr[NN + 1];
__device__ int      g_cursor[NN];
__device__ int      g_csrsrc[EE];

static inline int cdiv(long long a, long long b) { return (int)((a + b - 1) / b); }

// ---------------------------------------------------------------------------
// CSR construction
// ---------------------------------------------------------------------------
__global__ void deg_reset(int* deg, int n) {
    int i = blockIdx.x * blockDim.x + threadIdx.x;
    if (i < n) deg[i] = 0;
}
__global__ void deg_count(const int* __restrict__ ei, int* __restrict__ deg, int E) {
    int e = blockIdx.x * blockDim.x + threadIdx.x;
    if (e < E) atomicAdd(deg + ei[E + e], 1);
}
__global__ __launch_bounds__(1024)
void scan_kernel(const int* __restrict__ deg, int* __restrict__ rowptr,
                 int* __restrict__ cursor, int n)
{
    __shared__ int part[1024];
    int tid = threadIdx.x;
    int chunk = (n + 1023) / 1024;
    int base = tid * chunk;
    int s = 0;
    for (int i = 0; i < chunk; i++) {
        int idx = base + i;
        if (idx < n) s += deg[idx];
    }
    part[tid] = s;
    __syncthreads();
    for (int off = 1; off < 1024; off <<= 1) {
        int v = (tid >= off) ? part[tid - off] : 0;
        __syncthreads();
        part[tid] += v;
        __syncthreads();
    }
    int run = (tid == 0) ? 0 : part[tid - 1];
    for (int i = 0; i < chunk; i++) {
        int idx = base + i;
        if (idx < n) {
            rowptr[idx] = run;
            cursor[idx] = run;
            run += deg[idx];
        }
    }
    if (tid == 0) rowptr[n] = part[1023];
}
__global__ void csr_scatter(const int* __restrict__ ei, int* __restrict__ cursor,
                            int* __restrict__ csrsrc, int E)
{
    int e = blockIdx.x * blockDim.x + threadIdx.x;
    if (e >= E) return;
    int d = ei[E + e];
    int pos = atomicAdd(cursor + d, 1);
    csrsrc[pos] = ei[e];
}

// ---------------------------------------------------------------------------
// w~s[h][k] = sum_c W0[k][h*64+c]*as0[h][c]  (and w~d from ad0).
// Folds the attention vectors through W0 so logits come straight from x.
// ---------------------------------------------------------------------------
__global__ void prep_wt(const float* __restrict__ W0,
                        const float* __restrict__ as0,
                        const float* __restrict__ ad0,
                        float* __restrict__ wt)
{
    int t = threadIdx.x;          // 256 threads: (h,k)
    int h = t >> 6, k = t & 63;
    float ss = 0.f, sd = 0.f;
    for (int c = 0; c < 64; c++) {
        float w = W0[k * 256 + h * 64 + c];
        ss += w * as0[h * 64 + c];
        sd += w * ad0[h * 64 + c];
    }
    wt[h * 64 + k]       = ss;
    wt[256 + h * 64 + k] = sd;
}

// ---------------------------------------------------------------------------
// Layer-0 logits directly from x: asrc[n,h] = dot(x[n], w~s[h]).
// Warp per node; lane owns channel pair (2l, 2l+1).
// ---------------------------------------------------------------------------
__global__ void alpha0_kernel(const float* __restrict__ x,
                              const float* __restrict__ wt,
                              float* __restrict__ asrc, float* __restrict__ adst, int N)
{
    __shared__ float ws[8][64];
    for (int i = threadIdx.x; i < 512; i += blockDim.x)
        ((float*)ws)[i] = wt[i];
    __syncthreads();

    int gw   = (int)((blockIdx.x * (long long)blockDim.x + threadIdx.x) >> 5);
    int lane = threadIdx.x & 31;
    if (gw >= N) return;

    float2 xv = *(const float2*)(x + (size_t)gw * 64 + lane * 2);
    float s[8];
    #pragma unroll
    for (int h = 0; h < 8; h++)
        s[h] = xv.x * ws[h][lane * 2] + xv.y * ws[h][lane * 2 + 1];
    #pragma unroll
    for (int o = 16; o; o >>= 1)
        #pragma unroll
        for (int h = 0; h < 8; h++)
            s[h] += __shfl_xor_sync(0xffffffffu, s[h], o);

    if (lane < 4)       asrc[(size_t)gw * 4 + lane]       = s[lane];
    else if (lane < 8)  adst[(size_t)gw * 4 + (lane - 4)] = s[lane];
}

// ---------------------------------------------------------------------------
// Layer-0 gather on x (linearity: agg_h = (sum alpha_h * x[src]) @ W0_h later).
// Warp per node; lane owns x-channel pair (2l,2l+1) for ALL 4 heads.
// den accumulated privately per lane (all lanes compute identical alphas).
// Writes X4[n][h*64+k] = dinv_h * sum_e alpha_e x[src][k]  (0.25 folded in).
// ---------------------------------------------------------------------------
__device__ __forceinline__ float leaky02(float v) { return v > 0.f ? v : 0.2f * v; }

__global__ void gatherx_kernel(const int* __restrict__ rowptr,
                               const int* __restrict__ csrsrc,
                               const float* __restrict__ asrc,
                               const float* __restrict__ adst,
                               const float* __restrict__ x,
                               float* __restrict__ X4, int N)
{
    int gw   = (int)((blockIdx.x * (long long)blockDim.x + threadIdx.x) >> 5);
    int lane = threadIdx.x & 31;
    if (gw >= N) return;

    int beg = rowptr[gw], end = rowptr[gw + 1];
    float4 ad = *(const float4*)(adst + (size_t)gw * 4);

    float acc[4][2] = {};
    float den[4] = {};

    for (int j = beg; j < end; j++) {
        int s = csrsrc[j];
        float4 a = *(const float4*)(asrc + (size_t)s * 4);
        float al0 = __expf(leaky02(a.x + ad.x));
        float al1 = __expf(leaky02(a.y + ad.y));
        float al2 = __expf(leaky02(a.z + ad.z));
        float al3 = __expf(leaky02(a.w + ad.w));
        den[0] += al0; den[1] += al1; den[2] += al2; den[3] += al3;
        float2 xv = *(const float2*)(x + (size_t)s * 64 + lane * 2);
        acc[0][0] += xv.x * al0; acc[0][1] += xv.y * al0;
        acc[1][0] += xv.x * al1; acc[1][1] += xv.y * al1;
        acc[2][0] += xv.x * al2; acc[2][1] += xv.y * al2;
        acc[3][0] += xv.x * al3; acc[3][1] += xv.y * al3;
    }

    #pragma unroll
    for (int h = 0; h < 4; h++) {
        float di = 0.25f / (den[h] + 1e-16f);     // folds head-mean 0.25
        float2 o = make_float2(acc[h][0] * di, acc[h][1] * di);
        *(float2*)(X4 + (size_t)gw * 256 + h * 64 + lane * 2) = o;
    }
}

// ---------------------------------------------------------------------------
// Block-diagonal GEMM: out0[n][c] = relu( sum_{h,k} X4[n][h*64+k]*W0[k][h*64+c]
//                                         + b0[c] )
// BM=128, BN=64, BK=16, 128 threads (4 warps, warp tile 32x64, lane 8x8) —
// same conflict-free fragment pattern as sgemm128. B-tile load remaps the
// block-diagonal W0 access; K = 256 fixed.
// ---------------------------------------------------------------------------
__global__ __launch_bounds__(128)
void bdgemm(const float* __restrict__ X4, const float* __restrict__ W0,
            const float* __restrict__ bias, float* __restrict__ C, int M)
{
    const int BM = 128, BK = 16, K = 256;
    __shared__ __align__(16) float As[BK][BM + 4];
    __shared__ __align__(16) float Bs[BK][64];

    int tid  = threadIdx.x;
    int wid  = tid >> 5, lane = tid & 31;
    int r    = lane >> 3;
    int c    = lane & 7;
    int rowBase = blockIdx.y * BM;

    int trow  = wid * 32 + r * 8;
    int tcol0 = c * 4;
    int tcol1 = 32 + c * 4;

    float acc[8][8] = {};

    for (int k0 = 0; k0 < K; k0 += BK) {
        // A tile: 128 rows x 16 k. 512 float4; 4 per thread, sector-friendly.
        #pragma unroll
        for (int i = 0; i < 4; i++) {
            int idx = tid + i * 128;
            int row = idx >> 2;
            int c4  = (idx & 3) * 4;
            int gr  = rowBase + row;
            float4 av = make_float4(0.f, 0.f, 0.f, 0.f);
            if (gr < M) av = *(const float4*)(X4 + (size_t)gr * K + k0 + c4);
            As[c4 + 0][row] = av.x; As[c4 + 1][row] = av.y;
            As[c4 + 2][row] = av.z; As[c4 + 3][row] = av.w;
        }
        // B tile: 16 x 64 with block-diagonal remap of W0 [64,256].
        #pragma unroll
        for (int i = 0; i < 2; i++) {
            int idx = tid + i * 128;          // 0..255
            int br  = idx >> 4;               // 0..15
            int bc  = (idx & 15) * 4;         // 0..60
            int j   = k0 + br;                // global k in [0,256)
            const float* src = W0 + (size_t)(j & 63) * 256 + (j >> 6) * 64 + bc;
            *(float4*)&Bs[br][bc] = *(const float4*)src;
        }
        __syncthreads();

        #pragma unroll
        for (int k = 0; k < BK; k++) {
            float a[8], b[8];
            *(float4*)&a[0] = *(const float4*)&As[k][trow];
            *(float4*)&a[4] = *(const float4*)&As[k][trow + 4];
            *(float4*)&b[0] = *(const float4*)&Bs[k][tcol0];
            *(float4*)&b[4] = *(const float4*)&Bs[k][tcol1];
            #pragma unroll
            for (int m = 0; m < 8; m++)
                #pragma unroll
                for (int n = 0; n < 8; n++)
                    acc[m][n] += a[m] * b[n];
        }
        __syncthreads();
    }

    #pragma unroll
    for (int m = 0; m < 8; m++) {
        int gr = rowBase + trow + m;
        if (gr >= M) continue;
        #pragma unroll
        for (int half = 0; half < 2; half++) {
            int cb = (half == 0) ? tcol0 : tcol1;
            #pragma unroll
            for (int n = 0; n < 4; n++) {
                int gc = cb + n;
                float v = acc[m][half * 4 + n] + bias[gc];
                C[(size_t)gr * 64 + gc] = fmaxf(v, 0.f);
            }
        }
    }
}

// ---------------------------------------------------------------------------
// sgemm64: BM=BN=64, BK=16, 256 threads, 4x4 micro-tile (small-N layers).
// ---------------------------------------------------------------------------
__global__ __launch_bounds__(256)
void sgemm64(const float* __restrict__ A, const float* __restrict__ B,
             const float* __restrict__ bias, float* __restrict__ C,
             int M, int N, int K, int relu)
{
    const int BM = 64, BN = 64, BK = 16;
    __shared__ __align__(16) float As[BK][BM + 4];
    __shared__ __align__(16) float Bs[BK][BN];

    int tid = threadIdx.x;
    int tx  = tid & 15;
    int ty  = tid >> 4;
    int rowBase = blockIdx.y * BM;
    int colBase = blockIdx.x * BN;
    int ar = tid >> 2;
    int ac = (tid & 3) * 4;

    float acc[4][4] = {};

    for (int k0 = 0; k0 < K; k0 += BK) {
        float4 av = make_float4(0.f, 0.f, 0.f, 0.f);
        int gr = rowBase + ar;
        if (gr < M) av = *(const float4*)(A + (size_t)gr * K + k0 + ac);
        As[ac + 0][ar] = av.x; As[ac + 1][ar] = av.y;
        As[ac + 2][ar] = av.z; As[ac + 3][ar] = av.w;

        #pragma unroll
        for (int i = 0; i < 4; i++) {
            int idx = tid + i * 256;
            int r = idx >> 6, c = idx & 63;
            int gc = colBase + c;
            Bs[r][c] = (gc < N) ? B[(size_t)(k0 + r) * N + gc] : 0.f;
        }
        __syncthreads();

        #pragma unroll
        for (int k = 0; k < BK; k++) {
            float4 a4 = *(const float4*)&As[k][ty * 4];
            float4 b4 = *(const float4*)&Bs[k][tx * 4];
            float am[4] = {a4.x, a4.y, a4.z, a4.w};
            float bm[4] = {b4.x, b4.y, b4.z, b4.w};
            #pragma unroll
            for (int m = 0; m < 4; m++)
                #pragma unroll
                for (int n = 0; n < 4; n++)
                    acc[m][n] += am[m] * bm[n];
        }
        __syncthreads();
    }

    #pragma unroll
    for (int m = 0; m < 4; m++) {
        int gr = rowBase + ty * 4 + m;
        if (gr >= M) continue;
        #pragma unroll
        for (int n = 0; n < 4; n++) {
            int gc = colBase + tx * 4 + n;
            if (gc >= N) continue;
            float v = acc[m][n];
            if (bias) v += bias[gc];
            if (relu) v = fmaxf(v, 0.f);
            C[(size_t)gr * N + gc] = v;
        }
    }
}

// ---------------------------------------------------------------------------
// sgemm128: BM=BN=128, BK=8, warp-tiled 8x8 micro-tile, conflict-free LDS.
// (h1 / d4.)
// ---------------------------------------------------------------------------
__global__ __launch_bounds__(256, 2)
void sgemm128(const float* __restrict__ A, const float* __restrict__ B,
              const float* __restrict__ bias, float* __restrict__ C,
              int M, int N, int K, int relu)
{
    const int BM = 128, BN = 128, BK = 8;
    __shared__ __align__(16) float As[BK][BM + 4];
    __shared__ __align__(16) float Bs[BK][BN];

    int tid  = threadIdx.x;
    int wid  = tid >> 5, lane = tid & 31;
    int wm   = wid & 3;
    int wn   = wid >> 2;
    int r    = lane >> 3;
    int c    = lane & 7;
    int rowBase = blockIdx.y * BM;
    int colBase = blockIdx.x * BN;

    int trow  = wm * 32 + r * 8;
    int tcol0 = wn * 64 + c * 4;
    int tcol1 = wn * 64 + 32 + c * 4;

    int ar = tid >> 1;
    int ac = (tid & 1) * 4;
    int br = tid >> 5;
    int bc = (tid & 31) * 4;

    float acc[8][8] = {};

    for (int k0 = 0; k0 < K; k0 += BK) {
        float4 av = make_float4(0.f, 0.f, 0.f, 0.f);
        int gr = rowBase + ar;
        if (gr < M) av = *(const float4*)(A + (size_t)gr * K + k0 + ac);
        As[ac + 0][ar] = av.x; As[ac + 1][ar] = av.y;
        As[ac + 2][ar] = av.z; As[ac + 3][ar] = av.w;

        int gc = colBase + bc;
        float4 bv;
        if (gc + 3 < N) {
            bv = *(const float4*)(B + (size_t)(k0 + br) * N + gc);
        } else {
            bv.x = (gc + 0 < N) ? B[(size_t)(k0 + br) * N + gc + 0] : 0.f;
            bv.y = (gc + 1 < N) ? B[(size_t)(k0 + br) * N + gc + 1] : 0.f;
            bv.z = (gc + 2 < N) ? B[(size_t)(k0 + br) * N + gc + 2] : 0.f;
            bv.w = (gc + 3 < N) ? B[(size_t)(k0 + br) * N + gc + 3] : 0.f;
        }
        *(float4*)&Bs[br][bc] = bv;
        __syncthreads();

        #pragma unroll
        for (int k = 0; k < BK; k++) {
            float a[8], b[8];
            *(float4*)&a[0] = *(const float4*)&As[k][trow];
            *(float4*)&a[4] = *(const float4*)&As[k][trow + 4];
            *(float4*)&b[0] = *(const float4*)&Bs[k][tcol0];
            *(float4*)&b[4] = *(const float4*)&Bs[k][tcol1];
            #pragma unroll
            for (int m = 0; m < 8; m++)
                #pragma unroll
                for (int n = 0; n < 8; n++)
                    acc[m][n] += a[m] * b[n];
        }
        __syncthreads();
    }

    #pragma unroll
    for (int m = 0; m < 8; m++) {
        int gr = rowBase + trow + m;
        if (gr >= M) continue;
        #pragma unroll
        for (int half = 0; half < 2; half++) {
            int cb = (half == 0) ? tcol0 : tcol1;
            #pragma unroll
            for (int n = 0; n < 4; n++) {
                int gc = colBase + cb + n;
                if (gc >= N) continue;
                float v = acc[m][half * 4 + n];
                if (bias) v += bias[gc];
                if (relu) v = fmaxf(v, 0.f);
                C[(size_t)gr * N + gc] = v;
            }
        }
    }
}

// ---------------------------------------------------------------------------
// Per-node attention logits from h (layer 1; warp per node)
// ---------------------------------------------------------------------------
template <int C>
__global__ void alpha_kernel(const float* __restrict__ h,
                             const float* __restrict__ a_s,
                             const float* __restrict__ a_d,
                             float* __restrict__ asrc, float* __restrict__ adst, int N)
{
    int gw   = (int)((blockIdx.x * (long long)blockDim.x + threadIdx.x) >> 5);
    int lane = threadIdx.x & 31;
    if (gw >= N) return;
    const float* hr = h + (size_t)gw * 4 * C;
    #pragma unroll
    for (int hh = 0; hh < 4; hh++) {
        float s1 = 0.f, s2 = 0.f;
        #pragma unroll
        for (int c = lane; c < C; c += 32) {
            float hv = hr[hh * C + c];
            s1 += hv * a_s[hh * C + c];
            s2 += hv * a_d[hh * C + c];
        }
        #pragma unroll
        for (int o = 16; o; o >>= 1) {
            s1 += __shfl_down_sync(0xffffffffu, s1, o);
            s2 += __shfl_down_sync(0xffffffffu, s2, o);
        }
        if (lane == 0) {
            asrc[(size_t)gw * 4 + hh] = s1;
            adst[(size_t)gw * 4 + hh] = s2;
        }
    }
}

// ---------------------------------------------------------------------------
// Single-pass fused GAT aggregation on h (layer 1). R13 winner.
// ---------------------------------------------------------------------------
template <int C>
__global__ void gather_kernel(const int* __restrict__ rowptr,
                              const int* __restrict__ csrsrc,
                              const float* __restrict__ asrc,
                              const float* __restrict__ adst,
                              const float* __restrict__ h,
                              const float* __restrict__ bias,
                              float* __restrict__ out, int N)
{
    constexpr int P = (4 * C) / 32;
    int gw   = (int)((blockIdx.x * (long long)blockDim.x + threadIdx.x) >> 5);
    int lane = threadIdx.x & 31;
    if (gw >= N) return;

    int beg = rowptr[gw], end = rowptr[gw + 1];
    int hh = lane >> 3;
    float adh = adst[(size_t)gw * 4 + hh];

    float acc[P];
    #pragma unroll
    for (int i = 0; i < P; i++) acc[i] = 0.f;
    float den = 0.f;

    for (int j = beg; j < end; j++) {
        int s = csrsrc[j];
        float al = __expf(leaky02(asrc[(size_t)s * 4 + hh] + adh));
        den += al;
        const float4* hp = (const float4*)(h + (size_t)s * 4 * C + lane * P);
        #pragma unroll
        for (int q = 0; q < P / 4; q++) {
            float4 hv = hp[q];
            acc[q * 4 + 0] += hv.x * al;
            acc[q * 4 + 1] += hv.y * al;
            acc[q * 4 + 2] += hv.z * al;
            acc[q * 4 + 3] += hv.w * al;
        }
    }

    float dinv = 0.25f / (den + 1e-16f);
    #pragma unroll
    for (int i = 0; i < P; i++) acc[i] *= dinv;

    #pragma unroll
    for (int o = 8; o < 32; o <<= 1)
        #pragma unroll
        for (int i = 0; i < P; i++)
            acc[i] += __shfl_xor_sync(0xffffffffu, acc[i], o);

    if (lane < 8) {
        int cb = lane * P;
        #pragma unroll
        for (int q = 0; q < P / 4; q++) {
            float4 v;
            v.x = fmaxf(acc[q * 4 + 0] + bias[cb + q * 4 + 0], 0.f);
            v.y = fmaxf(acc[q * 4 + 1] + bias[cb + q * 4 + 1], 0.f);
            v.z = fmaxf(acc[q * 4 + 2] + bias[cb + q * 4 + 2], 0.f);
            v.w = fmaxf(acc[q * 4 + 3] + bias[cb + q * 4 + 3], 0.f);
            *(float4*)(out + (size_t)gw * C + cb + q * 4) = v;
        }
    }
}

__global__ void link_kernel(const int* __restrict__ eli, const float* __restrict__ z,
                            float* __restrict__ out, int NL)
{
    int i = blockIdx.x * blockDim.x + threadIdx.x;
    if (i >= NL) return;
    int a = eli[i], b = eli[NL + i];
    const float4* za = (const float4*)(z + (size_t)a * 32);
    const float4* zb = (const float4*)(z + (size_t)b * 32);
    float s = 0.f;
    #pragma unroll
    for (int j = 0; j < 8; j++) {
        float4 u = za[j], v = zb[j];
        s += u.x * v.x + u.y * v.y + u.z * v.z + u.w * v.w;
    }
    out[i] = s;
}

// ---------------------------------------------------------------------------
// Launch
// ---------------------------------------------------------------------------
extern "C" void kernel_launch(void* const* d_in, const int* in_sizes, int n_in,
                              void* d_out, int out_size)
{
    const float* x   = (const float*)d_in[0];
    const int*   ei  = (const int*)  d_in[1];
    const int*   eli = (const int*)  d_in[2];
    const float* W0  = (const float*)d_in[3];
    const float* as0 = (const float*)d_in[4];
    const float* ad0 = (const float*)d_in[5];
    const float* b0  = (const float*)d_in[6];
    const float* W1  = (const float*)d_in[7];
    const float* as1 = (const float*)d_in[8];
    const float* ad1 = (const float*)d_in[9];
    const float* b1  = (const float*)d_in[10];
    const float* lw  = (const float*)d_in[11];
    const float* lb  = (const float*)d_in[12];
    const float* d1w = (const float*)d_in[13];
    const float* d1b = (const float*)d_in[14];
    const float* d2w = (const float*)d_in[15];
    const float* d2b = (const float*)d_in[16];
    const float* d3w = (const float*)d_in[17];
    const float* d3b = (const float*)d_in[18];
    const float* d4w = (const float*)d_in[19];
    const float* d4b = (const float*)d_in[20];

    int N  = in_sizes[0] / 64;
    int E  = in_sizes[1] / 2;
    int NL = in_sizes[2] / 2;
    float* out = (float*)d_out;

    float *X4, *out0, *h1, *out1, *z, *asrc, *adst, *wt, *e1, *e2, *e3;
    int *deg, *rowptr, *cursor, *csrsrc;
    cudaGetSymbolAddress((void**)&X4,   g_X4);
    cudaGetSymbolAddress((void**)&out0, g_out0);
    cudaGetSymbolAddress((void**)&h1,   g_h1);
    cudaGetSymbolAddress((void**)&out1, g_out1);
    cudaGetSymbolAddress((void**)&z,    g_z);
    cudaGetSymbolAddress((void**)&asrc, g_asrc);
    cudaGetSymbolAddress((void**)&adst, g_adst);
    cudaGetSymbolAddress((void**)&wt,   g_wt);
    cudaGetSymbolAddress((void**)&e1,   g_e1);
    cudaGetSymbolAddress((void**)&e2,   g_e2);
    cudaGetSymbolAddress((void**)&e3,   g_e3);
    cudaGetSymbolAddress((void**)&deg,    g_deg);
    cudaGetSymbolAddress((void**)&rowptr, g_rowptr);
    cudaGetSymbolAddress((void**)&cursor, g_cursor);
    cudaGetSymbolAddress((void**)&csrsrc, g_csrsrc);

    dim3 blk(256);
    int gE    = cdiv(E, 256);
    int gN    = cdiv(N, 256);
    int gR64  = cdiv(N, 64);
    int gR128 = cdiv(N, 128);
    int gWarp = cdiv((long long)N * 32, 256);

    // ------------------ CSR build (shared by both layers) ------------------
    deg_reset  <<<gN, blk>>>(deg, N);
    deg_count  <<<gE, blk>>>(ei, deg, E);
    scan_kernel<<<1, 1024>>>(deg, rowptr, cursor, N);
    csr_scatter<<<gE, blk>>>(ei, cursor, csrsrc, E);

    // ------------------ GAT layer 0 (linearity-restructured) ------------------
    prep_wt  <<<1, 256>>>(W0, as0, ad0, wt);
    alpha0_kernel<<<cdiv(N, 8), blk>>>(x, wt, asrc, adst, N);
    gatherx_kernel<<<gWarp, blk>>>(rowptr, csrsrc, asrc, adst, x, X4, N);
    bdgemm<<<dim3(1, gR128), 128>>>(X4, W0, b0, out0, N);

    // ------------------ GAT layer 1 (64 -> 4 x 32) ------------------
    sgemm128<<<dim3(1, gR128), blk>>>(out0, W1, nullptr, h1, N, 128, 64, 0);
    alpha_kernel<32><<<cdiv(N, 8), blk>>>(h1, as1, ad1, asrc, adst, N);
    gather_kernel<32><<<gWarp, blk>>>(rowptr, csrsrc, asrc, adst, h1, b1, out1, N);

    // ------------------ z = out1 @ lin_w + lin_b ------------------
    sgemm64<<<dim3(1, gR64), blk>>>(out1, lw, lb, z, N, 32, 32, 0);

    // ------------------ link decode -> d_out[0 : NL] ------------------
    link_kernel<<<cdiv(NL, 256), blk>>>(eli, z, out, NL);

    // ------------------ expression MLP -> d_out[NL : ] ------------------
    sgemm64 <<<dim3(1, gR64),  blk>>>(z,  d1w, d1b, e1, N, 32,  32, 1);
    sgemm64 <<<dim3(1, gR64),  blk>>>(e1, d2w, d2b, e2, N, 64,  32, 1);
    sgemm64 <<<dim3(2, gR64),  blk>>>(e2, d3w, d3b, e3, N, 96,  64, 1);
    sgemm128<<<dim3(4, gR128), blk>>>(e3, d4w, d4b, out + NL, N, 500, 96, 0);
}